// round 3
// baseline (speedup 1.0000x reference)
#include <cuda_runtime.h>
#include <cuda_bf16.h>

// ---------------------------------------------------------------------------
// CausalMLA  fp32 baseline
//   B=2, L=2048, D=2048, H=16, HD=128, LD=32
// Pipeline:
//   1) Q/K/V = x @ W + b            (3x SGEMM 4096x2048x2048)
//   2) RoPE (fused into compress)
//   3) qc/kc/vc = rot(q) @ Wc + bc  (per-head 128->32)
//   4) causal flash attention at head-dim 32
//   5) attn @ Wd + bd, transpose back to [B,L,D]
//   6) out = attn2 @ Wo + bo        (SGEMM 4096x2048x2048)
// ---------------------------------------------------------------------------

#define NTOK   4096      // B*L
#define DMODEL 2048
#define NHEAD  16
#define HDIM   128
#define LDIM   32
#define SEQ    2048
#define NBH    32        // B*H

// Scratch (static device globals; no runtime allocation allowed)
__device__ float g_Q [NTOK * DMODEL];
__device__ float g_K [NTOK * DMODEL];
__device__ float g_V [NTOK * DMODEL];
__device__ float g_qc[NBH * SEQ * LDIM];
__device__ float g_kc[NBH * SEQ * LDIM];
__device__ float g_vc[NBH * SEQ * LDIM];
__device__ float g_ac[NBH * SEQ * LDIM];
__device__ float g_a2[NTOK * DMODEL];

// ---------------------------------------------------------------------------
// SGEMM: C[M,N] = A[M,K] @ B[K,N] + bias[N]
// 128x128 block tile, BK=16, 8x8 per thread, 256 threads, smem double buffer.
// ---------------------------------------------------------------------------
__global__ __launch_bounds__(256) void sgemm_bias(
    const float* __restrict__ A, const float* __restrict__ B,
    const float* __restrict__ bias, float* __restrict__ C,
    int M, int N, int K)
{
    __shared__ __align__(16) float As[2][16][132];   // transposed, padded
    __shared__ __align__(16) float Bs[2][16][128];

    const int tid = threadIdx.x;
    const int tx  = tid & 15;     // output col group
    const int ty  = tid >> 4;     // output row group
    const int m0  = blockIdx.y * 128;
    const int n0  = blockIdx.x * 128;

    // A tile load mapping: 128 rows x 16 cols, 2 float4 per thread
    const int aRow = tid >> 2;          // 0..63
    const int aCol = (tid & 3) * 4;     // 0,4,8,12
    // B tile load mapping: 16 rows x 128 cols, 2 float4 per thread
    const int bRow = tid >> 5;          // 0..7
    const int bCol = (tid & 31) * 4;    // 0..124

    const float* Aptr = A + (size_t)(m0 + aRow) * K + aCol;
    const float* Bptr = B + (size_t)bRow * N + n0 + bCol;

    float4 a0, a1, b0, b1;
    // preload tile 0
    a0 = *(const float4*)(Aptr);
    a1 = *(const float4*)(Aptr + (size_t)64 * K);
    b0 = *(const float4*)(Bptr);
    b1 = *(const float4*)(Bptr + (size_t)8 * N);

    As[0][aCol + 0][aRow]      = a0.x;
    As[0][aCol + 1][aRow]      = a0.y;
    As[0][aCol + 2][aRow]      = a0.z;
    As[0][aCol + 3][aRow]      = a0.w;
    As[0][aCol + 0][aRow + 64] = a1.x;
    As[0][aCol + 1][aRow + 64] = a1.y;
    As[0][aCol + 2][aRow + 64] = a1.z;
    As[0][aCol + 3][aRow + 64] = a1.w;
    *(float4*)&Bs[0][bRow][bCol]     = b0;
    *(float4*)&Bs[0][bRow + 8][bCol] = b1;
    __syncthreads();

    float acc[8][8];
    #pragma unroll
    for (int i = 0; i < 8; ++i)
        #pragma unroll
        for (int j = 0; j < 8; ++j) acc[i][j] = 0.f;

    const int KT = K >> 4;
    for (int t = 0; t < KT; ++t) {
        const int cur = t & 1;
        if (t + 1 < KT) {
            const float* Ap = Aptr + (t + 1) * 16;
            const float* Bp = Bptr + (size_t)(t + 1) * 16 * N;
            a0 = *(const float4*)(Ap);
            a1 = *(const float4*)(Ap + (size_t)64 * K);
            b0 = *(const float4*)(Bp);
            b1 = *(const float4*)(Bp + (size_t)8 * N);
        }

        #pragma unroll
        for (int k = 0; k < 16; ++k) {
            float4 ra0 = *(const float4*)&As[cur][k][ty * 8];
            float4 ra1 = *(const float4*)&As[cur][k][ty * 8 + 4];
            float4 rb0 = *(const float4*)&Bs[cur][k][tx * 8];
            float4 rb1 = *(const float4*)&Bs[cur][k][tx * 8 + 4];
            float ar[8] = {ra0.x, ra0.y, ra0.z, ra0.w, ra1.x, ra1.y, ra1.z, ra1.w};
            float br[8] = {rb0.x, rb0.y, rb0.z, rb0.w, rb1.x, rb1.y, rb1.z, rb1.w};
            #pragma unroll
            for (int i = 0; i < 8; ++i)
                #pragma unroll
                for (int j = 0; j < 8; ++j)
                    acc[i][j] += ar[i] * br[j];
        }

        if (t + 1 < KT) {
            const int nxt = cur ^ 1;
            As[nxt][aCol + 0][aRow]      = a0.x;
            As[nxt][aCol + 1][aRow]      = a0.y;
            As[nxt][aCol + 2][aRow]      = a0.z;
            As[nxt][aCol + 3][aRow]      = a0.w;
            As[nxt][aCol + 0][aRow + 64] = a1.x;
            As[nxt][aCol + 1][aRow + 64] = a1.y;
            As[nxt][aCol + 2][aRow + 64] = a1.z;
            As[nxt][aCol + 3][aRow + 64] = a1.w;
            *(float4*)&Bs[nxt][bRow][bCol]     = b0;
            *(float4*)&Bs[nxt][bRow + 8][bCol] = b1;
        }
        __syncthreads();
    }

    const int row = m0 + ty * 8;
    const int col = n0 + tx * 8;
    float4 bv0 = *(const float4*)(bias + col);
    float4 bv1 = *(const float4*)(bias + col + 4);
    #pragma unroll
    for (int i = 0; i < 8; ++i) {
        float4 o0 = make_float4(acc[i][0] + bv0.x, acc[i][1] + bv0.y,
                                acc[i][2] + bv0.z, acc[i][3] + bv0.w);
        float4 o1 = make_float4(acc[i][4] + bv1.x, acc[i][5] + bv1.y,
                                acc[i][6] + bv1.z, acc[i][7] + bv1.w);
        *(float4*)(C + (size_t)(row + i) * N + col)     = o0;
        *(float4*)(C + (size_t)(row + i) * N + col + 4) = o1;
    }
}

// ---------------------------------------------------------------------------
// Compress: for each (token, head) row of X[NTOK, DMODEL] (layout [t][h*128+d]),
// optionally apply RoPE, then project 128 -> 32 with Wc[128,32] + bc[32].
// Output layout: out[(bh*SEQ + l)*32 + e] with bh = b*16 + h.
// One warp per row; 8 warps per block.
// ---------------------------------------------------------------------------
template<bool ROPE>
__global__ __launch_bounds__(256) void compress_kernel(
    const float* __restrict__ X, const float* __restrict__ Wc,
    const float* __restrict__ bc, const float* __restrict__ cosT,
    const float* __restrict__ sinT, float* __restrict__ out)
{
    __shared__ float Wcs[HDIM * LDIM];       // 16 KB
    __shared__ __align__(16) float rows[8][HDIM];

    const int tid  = threadIdx.x;
    const int lane = tid & 31;
    const int w    = tid >> 5;

    for (int i = tid; i < HDIM * LDIM; i += 256) Wcs[i] = Wc[i];
    __syncthreads();

    const int rid = blockIdx.x * 8 + w;          // 0 .. NTOK*NHEAD-1
    const int t   = rid >> 4;                    // token index 0..4095
    const int h   = rid & 15;
    const int l   = t & (SEQ - 1);

    float4 v = *(const float4*)(X + (size_t)t * DMODEL + h * HDIM + lane * 4);
    if (ROPE) {
        const float c0 = cosT[l * 64 + lane * 2];
        const float s0 = sinT[l * 64 + lane * 2];
        const float c1 = cosT[l * 64 + lane * 2 + 1];
        const float s1 = sinT[l * 64 + lane * 2 + 1];
        float e0 = v.x, o0 = v.y, e1 = v.z, o1 = v.w;
        v.x = e0 * c0 - o0 * s0;
        v.y = e0 * s0 + o0 * c0;
        v.z = e1 * c1 - o1 * s1;
        v.w = e1 * s1 + o1 * c1;
    }
    *(float4*)&rows[w][lane * 4] = v;
    __syncwarp();

    float acc = bc[lane];
    #pragma unroll
    for (int d = 0; d < HDIM; ++d)
        acc += rows[w][d] * Wcs[d * LDIM + lane];

    const int bh = (t >> 11) * NHEAD + h;        // b*16 + h
    out[((size_t)bh * SEQ + l) * LDIM + lane] = acc;
}

// ---------------------------------------------------------------------------
// Causal flash attention, head-dim 32, fp32, online softmax with 16-key chunks.
// One thread per query row, 128 queries per CTA, 128-key smem tiles.
// grid = (SEQ/128, NBH), block = 128.
// ---------------------------------------------------------------------------
__global__ __launch_bounds__(128) void flash_kernel(
    const float* __restrict__ QC, const float* __restrict__ KC,
    const float* __restrict__ VC, float* __restrict__ AC)
{
    __shared__ __align__(16) float kcs[128 * LDIM];   // 16 KB
    __shared__ __align__(16) float vcs[128 * LDIM];   // 16 KB

    const int tid = threadIdx.x;
    const int bh  = blockIdx.y;
    const int q0  = blockIdx.x * 128;
    const int qi  = q0 + tid;
    const float scale = 0.17677669529663687f;   // 1/sqrt(32)

    float qv[LDIM];
    {
        const float4* qp = (const float4*)(QC + ((size_t)bh * SEQ + qi) * LDIM);
        #pragma unroll
        for (int i = 0; i < 8; ++i) {
            float4 v = qp[i];
            qv[i * 4 + 0] = v.x * scale;
            qv[i * 4 + 1] = v.y * scale;
            qv[i * 4 + 2] = v.z * scale;
            qv[i * 4 + 3] = v.w * scale;
        }
    }

    float m = -1e30f, lsum = 0.f;
    float acc[LDIM];
    #pragma unroll
    for (int e = 0; e < LDIM; ++e) acc[e] = 0.f;

    const int ntiles = blockIdx.x + 1;
    for (int kt = 0; kt < ntiles; ++kt) {
        const int kstart = kt * 128;
        const float4* kg = (const float4*)(KC + ((size_t)bh * SEQ + kstart) * LDIM);
        const float4* vg = (const float4*)(VC + ((size_t)bh * SEQ + kstart) * LDIM);
        for (int idx = tid; idx < 128 * LDIM / 4; idx += 128) {
            ((float4*)kcs)[idx] = kg[idx];
            ((float4*)vcs)[idx] = vg[idx];
        }
        __syncthreads();

        const bool masked = (kt == blockIdx.x);   // diagonal tile

        #pragma unroll 1
        for (int c = 0; c < 8; ++c) {
            float sv[16];
            #pragma unroll
            for (int kk = 0; kk < 16; ++kk) {
                const float4* kr = (const float4*)(kcs + (c * 16 + kk) * LDIM);
                float d0 = 0.f, d1 = 0.f, d2 = 0.f, d3 = 0.f;
                #pragma unroll
                for (int e4 = 0; e4 < 8; ++e4) {
                    float4 kvv = kr[e4];
                    d0 += qv[e4 * 4 + 0] * kvv.x;
                    d1 += qv[e4 * 4 + 1] * kvv.y;
                    d2 += qv[e4 * 4 + 2] * kvv.z;
                    d3 += qv[e4 * 4 + 3] * kvv.w;
                }
                sv[kk] = (d0 + d1) + (d2 + d3);
            }
            if (masked) {
                #pragma unroll
                for (int kk = 0; kk < 16; ++kk)
                    if (kstart + c * 16 + kk > qi) sv[kk] = -1e30f;
            }
            float cmax = sv[0];
            #pragma unroll
            for (int kk = 1; kk < 16; ++kk) cmax = fmaxf(cmax, sv[kk]);
            const float mnew = fmaxf(m, cmax);
            const float r = __expf(m - mnew);
            lsum *= r;
            #pragma unroll
            for (int e = 0; e < LDIM; ++e) acc[e] *= r;
            #pragma unroll
            for (int kk = 0; kk < 16; ++kk) {
                const float p = __expf(sv[kk] - mnew);
                lsum += p;
                const float4* vr = (const float4*)(vcs + (c * 16 + kk) * LDIM);
                #pragma unroll
                for (int e4 = 0; e4 < 8; ++e4) {
                    float4 vv = vr[e4];
                    acc[e4 * 4 + 0] += p * vv.x;
                    acc[e4 * 4 + 1] += p * vv.y;
                    acc[e4 * 4 + 2] += p * vv.z;
                    acc[e4 * 4 + 3] += p * vv.w;
                }
            }
            m = mnew;
        }
        __syncthreads();
    }

    const float inv = 1.0f / lsum;
    float4* op = (float4*)(AC + ((size_t)bh * SEQ + qi) * LDIM);
    #pragma unroll
    for (int i = 0; i < 8; ++i) {
        float4 o;
        o.x = acc[i * 4 + 0] * inv;
        o.y = acc[i * 4 + 1] * inv;
        o.z = acc[i * 4 + 2] * inv;
        o.w = acc[i * 4 + 3] * inv;
        op[i] = o;
    }
}

// ---------------------------------------------------------------------------
// Decompress 32 -> 128 with Wd[32,128] + bd, and transpose [bh][l] -> [b,l][h].
// 8 rows per block of 256 threads.
// ---------------------------------------------------------------------------
__global__ __launch_bounds__(256) void decompress_kernel(
    const float* __restrict__ AC, const float* __restrict__ Wd,
    const float* __restrict__ bd, float* __restrict__ OUT)
{
    __shared__ float Wds[LDIM * HDIM];     // 16 KB
    __shared__ float as[8][LDIM];

    const int tid = threadIdx.x;
    for (int i = tid; i < LDIM * HDIM; i += 256) Wds[i] = Wd[i];
    {
        const int r = tid >> 5, e = tid & 31;
        const int gr = blockIdx.x * 8 + r;
        as[r][e] = AC[(size_t)gr * LDIM + e];
    }
    __syncthreads();

    #pragma unroll
    for (int i = 0; i < 4; ++i) {
        const int idx = tid + i * 256;
        const int r = idx >> 7, d = idx & 127;
        float acc = bd[d];
        #pragma unroll
        for (int e = 0; e < LDIM; ++e)
            acc += as[r][e] * Wds[e * HDIM + d];
        const int gr = blockIdx.x * 8 + r;
        const int bh = gr >> 11;            // / SEQ
        const int l  = gr & (SEQ - 1);
        const int b  = bh >> 4, h = bh & 15;
        OUT[((size_t)(b * SEQ + l)) * DMODEL + h * HDIM + d] = acc;
    }
}

// ---------------------------------------------------------------------------
// Launch
// ---------------------------------------------------------------------------
extern "C" void kernel_launch(void* const* d_in, const int* in_sizes, int n_in,
                              void* d_out, int out_size)
{
    const float* x    = (const float*)d_in[0];
    const float* cosT = (const float*)d_in[1];
    const float* sinT = (const float*)d_in[2];
    const float* Wq   = (const float*)d_in[3];
    const float* bq   = (const float*)d_in[4];
    const float* Wk   = (const float*)d_in[5];
    const float* bk   = (const float*)d_in[6];
    const float* Wv   = (const float*)d_in[7];
    const float* bv   = (const float*)d_in[8];
    const float* Wqc  = (const float*)d_in[9];
    const float* bqc  = (const float*)d_in[10];
    const float* Wkc  = (const float*)d_in[11];
    const float* bkc  = (const float*)d_in[12];
    const float* Wvc  = (const float*)d_in[13];
    const float* bvc  = (const float*)d_in[14];
    const float* Wd   = (const float*)d_in[15];
    const float* bd   = (const float*)d_in[16];
    const float* Wo   = (const float*)d_in[17];
    const float* bo   = (const float*)d_in[18];
    float* out = (float*)d_out;

    float *Q, *Kb, *Vb, *qc, *kc, *vc, *ac, *a2;
    cudaGetSymbolAddress((void**)&Q,  g_Q);
    cudaGetSymbolAddress((void**)&Kb, g_K);
    cudaGetSymbolAddress((void**)&Vb, g_V);
    cudaGetSymbolAddress((void**)&qc, g_qc);
    cudaGetSymbolAddress((void**)&kc, g_kc);
    cudaGetSymbolAddress((void**)&vc, g_vc);
    cudaGetSymbolAddress((void**)&ac, g_ac);
    cudaGetSymbolAddress((void**)&a2, g_a2);

    dim3 gg(DMODEL / 128, NTOK / 128);   // (16, 32)

    sgemm_bias<<<gg, 256>>>(x, Wq, bq, Q,  NTOK, DMODEL, DMODEL);
    sgemm_bias<<<gg, 256>>>(x, Wk, bk, Kb, NTOK, DMODEL, DMODEL);
    sgemm_bias<<<gg, 256>>>(x, Wv, bv, Vb, NTOK, DMODEL, DMODEL);

    const int nblocks = (NTOK * NHEAD) / 8;   // 8192
    compress_kernel<true ><<<nblocks, 256>>>(Q,  Wqc, bqc, cosT, sinT, qc);
    compress_kernel<true ><<<nblocks, 256>>>(Kb, Wkc, bkc, cosT, sinT, kc);
    compress_kernel<false><<<nblocks, 256>>>(Vb, Wvc, bvc, cosT, sinT, vc);

    flash_kernel<<<dim3(SEQ / 128, NBH), 128>>>(qc, kc, vc, ac);

    decompress_kernel<<<nblocks, 256>>>(ac, Wd, bd, a2);

    sgemm_bias<<<gg, 256>>>(a2, Wo, bo, out, NTOK, DMODEL, DMODEL);
}